// round 14
// baseline (speedup 1.0000x reference)
#include <cuda_runtime.h>
#include <cstdint>

#define NN 20000
#define EE 320000
#define FF 8
#define TT 12
#define UU 256
#define FT 96   // FF*TT
#define FT4 24  // FT/4
#define EQ (EE / 4)          // edges per thread (4 each)
#define CAP 64               // slots per node
#define PLACE_BLKS ((EQ + 1023) / 1024)   // 79

// ---------------- device scratch ----------------
__device__ unsigned g_dc[2 * NN];    // [0,NN): weighted deg (float bits), [NN,2NN): count
__device__ uint2 g_slot[NN * CAP];   // per-dst buckets: (src, w-bits)
__device__ unsigned g_Mhi[FF * 512]; // tf32 hi of folded gate weights, col = 2u(+1 for h)
__device__ unsigned g_Mlo[FF * 512]; // tf32 lo residual
__device__ float g_czh[512];         // biases, col-interleaved (z,h); z prescaled 0.5
__device__ float g_p[TT];            // 0.5 * softmax(attention)

// ---------------- helpers ----------------
__device__ __forceinline__ float tanh_a(float x) {
    float y; asm("tanh.approx.f32 %0, %1;" : "=f"(y) : "f"(x)); return y;
}
__device__ __forceinline__ uint32_t to_tf32(float x) {
    uint32_t r; asm("cvt.rna.tf32.f32 %0, %1;" : "=r"(r) : "f"(x)); return r;
}
__device__ __forceinline__ void mma_tf32(float& c0, float& c1, float& c2, float& c3,
                                         uint32_t a0, uint32_t a1, uint32_t a2, uint32_t a3,
                                         uint32_t b0, uint32_t b1) {
    asm volatile("mma.sync.aligned.m16n8k8.row.col.f32.tf32.tf32.f32 "
                 "{%0,%1,%2,%3}, {%4,%5,%6,%7}, {%8,%9}, {%0,%1,%2,%3};"
                 : "+f"(c0), "+f"(c1), "+f"(c2), "+f"(c3)
                 : "r"(a0), "r"(a1), "r"(a2), "r"(a3), "r"(b0), "r"(b1));
}
__device__ __forceinline__ float4 fma4s(float s, float4 v, float4 a) {
    a.x = fmaf(s, v.x, a.x); a.y = fmaf(s, v.y, a.y);
    a.z = fmaf(s, v.z, a.z); a.w = fmaf(s, v.w, a.w);
    return a;
}

// ---------------- phase 1 (fused): edge placement + weight fold + softmax ----------------
__global__ void __launch_bounds__(1024) k_placeprep(
        const int* __restrict__ ei, const float* __restrict__ w,
        const float* __restrict__ Wz, const float* __restrict__ Lzw,
        const float* __restrict__ bz, const float* __restrict__ Lzb,
        const float* __restrict__ Wh, const float* __restrict__ Lhw,
        const float* __restrict__ bh, const float* __restrict__ Lhb,
        const float* __restrict__ att) {
    int blk = blockIdx.x;
    int tid = threadIdx.x;

    if (blk < PLACE_BLKS) {
        int t = blk * 1024 + tid;
        if (t >= EQ) return;
        int   src[4], dst[4];
        float wv[4];
#pragma unroll
        for (int j = 0; j < 4; j++) {
            int e = t + j * EQ;
            src[j] = __ldg(ei + e);
            dst[j] = __ldg(ei + EE + e);
            wv[j]  = __ldg(w + e);
        }
#pragma unroll
        for (int j = 0; j < 4; j++) {
            atomicAdd(reinterpret_cast<float*>(&g_dc[dst[j]]), wv[j]);
            int p = atomicAdd(reinterpret_cast<int*>(&g_dc[NN + dst[j]]), 1);
            if (p < CAP)
                g_slot[dst[j] * CAP + p] =
                    make_uint2((unsigned)src[j], __float_as_uint(wv[j]));
        }
        return;
    }

    int fb = blk - PLACE_BLKS;
    if (fb == 18) {
        if (tid == 0) {
            float m = -1e30f;
            for (int t = 0; t < TT; t++) m = fmaxf(m, att[t]);
            float e[TT], s = 0.0f;
            for (int t = 0; t < TT; t++) { e[t] = __expf(att[t] - m); s += e[t]; }
            float inv = 0.5f / s;
            for (int t = 0; t < TT; t++) g_p[t] = e[t] * inv;
        }
        return;
    }

    // weight fold: fb 0..8 -> z (cols 2u), 9..17 -> h (cols 2u+1); f = 0..7, 8 = bias
    bool isz = fb < 9;
    int f = isz ? fb : fb - 9;
    const float* W  = isz ? Wz : Wh;
    const float* L  = isz ? Lzw : Lhw;
    const float* b  = isz ? bz : bh;
    const float* Lb = isz ? Lzb : Lhb;
    float scale = isz ? 0.5f : 1.0f;                   // tanh(az/2) prescale on z
    int off = isz ? 0 : 1;

    __shared__ float srow[UU];
    __shared__ float part[4][UU];
    int u  = tid & 255;
    int kq = tid >> 8;                                 // 0..3
    if (tid < UU) srow[tid] = (f < FF) ? W[f * UU + tid] : b[tid];
    __syncthreads();

    float s = 0.0f;
    int k0 = kq * 64;
#pragma unroll
    for (int k = 0; k < 64; k++)
        s = fmaf(srow[k0 + k], __ldg(L + (size_t)(k0 + k) * UU + u), s);
    part[kq][u] = s;
    __syncthreads();

    if (tid < UU) {
        float tot = part[0][tid] + part[1][tid] + part[2][tid] + part[3][tid];
        if (f < FF) {
            float val = scale * tot;
            uint32_t hi = to_tf32(val);
            float lof = val - __uint_as_float(hi);
            g_Mhi[f * 512 + 2 * tid + off] = hi;
            g_Mlo[f * 512 + 2 * tid + off] = to_tf32(lof);
        } else {
            g_czh[2 * tid + off] = scale * (tot + Lb[tid]);
        }
    }
}

// ---------------- phase 2: gather + tensor-core gates + epilogue ----------------
#define NPB 8
__global__ void __launch_bounds__(UU, 3) k_dense(const float4* __restrict__ x4,
                                                 const float* __restrict__ lin_w,
                                                 const float* __restrict__ lin_b,
                                                 float* __restrict__ out) {
    // sYA: A matrix, rows = t*8+n (96), cols = f (8), row stride 9 (bank spread)
    __shared__ __align__(16) float sYA[96 * 9];
    __shared__ float sH[NPB][257];
    __shared__ __align__(16) float sp[TT];
    __shared__ __align__(8) float sCzh[512];

    int u = threadIdx.x;
    int lane = u & 31;
    int wid = u >> 5;
    int n0 = blockIdx.x * NPB;

    // ---- gather: warp w aggregates node n0+w; scatter into sYA (t*8+n, f) ----
    {
        int node = n0 + wid;
        int cn = (int)g_dc[NN + node];
        if (cn > CAP) cn = CAP;
        float degn = __uint_as_float(g_dc[node]) + 1.0f;   // +1 self-loop
        float dinvn = rsqrtf(degn);
        int ln = (lane < FT4) ? lane : 0;
        float4 a0 = __ldg(x4 + (size_t)node * FT4 + ln);
        float s = dinvn * dinvn;
        a0.x *= s; a0.y *= s; a0.z *= s; a0.w *= s;
        float4 a1 = make_float4(0.f, 0.f, 0.f, 0.f);

        const uint2* sl = g_slot + (size_t)node * CAP;
        int i = 0;
        for (; i + 2 <= cn; i += 2) {
            uint2 e0 = __ldg(sl + i);
            uint2 e1 = __ldg(sl + i + 1);
            float ds0 = __uint_as_float(g_dc[e0.x]) + 1.0f;
            float ds1 = __uint_as_float(g_dc[e1.x]) + 1.0f;
            float4 v0 = __ldg(x4 + (size_t)e0.x * FT4 + ln);
            float4 v1 = __ldg(x4 + (size_t)e1.x * FT4 + ln);
            a0 = fma4s(dinvn * __uint_as_float(e0.y) * rsqrtf(ds0), v0, a0);
            a1 = fma4s(dinvn * __uint_as_float(e1.y) * rsqrtf(ds1), v1, a1);
        }
        if (i < cn) {
            uint2 e = __ldg(sl + i);
            float ds = __uint_as_float(g_dc[e.x]) + 1.0f;
            float4 v = __ldg(x4 + (size_t)e.x * FT4 + ln);
            a0 = fma4s(dinvn * __uint_as_float(e.y) * rsqrtf(ds), v, a0);
        }
        a0.x += a1.x; a0.y += a1.y; a0.z += a1.z; a0.w += a1.w;
        if (lane < FT4) {
            float v[4] = {a0.x, a0.y, a0.z, a0.w};
            int base = lane * 4;
#pragma unroll
            for (int j = 0; j < 4; j++) {
                int idx = base + j;          // = f*12 + t
                int f = idx / 12;
                int t = idx - f * 12;
                sYA[(t * 8 + wid) * 9 + f] = v[j];
            }
        }
    }
    if (u < TT) sp[u] = g_p[u];
    sCzh[u] = g_czh[u];
    sCzh[u + 256] = g_czh[u + 256];
    __syncthreads();

    // ---- gates via 3xTF32 mma: warp covers cols [wid*64, wid*64+64) ----
    {
        int g = lane >> 2;      // groupID: row-within-tile / B col-within-tile
        int c = lane & 3;       // k-row selector / output col pair
        int colbase = wid * 64;

        uint32_t bhi0[8], bhi1[8], blo0[8], blo1[8];
#pragma unroll
        for (int j = 0; j < 8; j++) {
            int col = colbase + j * 8 + g;
            bhi0[j] = __ldg(&g_Mhi[c * 512 + col]);
            bhi1[j] = __ldg(&g_Mhi[(c + 4) * 512 + col]);
            blo0[j] = __ldg(&g_Mlo[c * 512 + col]);
            blo1[j] = __ldg(&g_Mlo[(c + 4) * 512 + col]);
        }
        float acc[8];
#pragma unroll
        for (int j = 0; j < 8; j++) acc[j] = 0.0f;

        const float2* sp2 = reinterpret_cast<const float2*>(sp);
#pragma unroll
        for (int mt = 0; mt < 6; mt++) {
            int r0 = (mt * 16 + g) * 9;
            float ar0 = sYA[r0 + c];
            float ar1 = sYA[r0 + 72 + c];        // row+8 -> +8*9
            float ar2 = sYA[r0 + c + 4];
            float ar3 = sYA[r0 + 72 + c + 4];
            uint32_t ah0 = to_tf32(ar0), ah1 = to_tf32(ar1);
            uint32_t ah2 = to_tf32(ar2), ah3 = to_tf32(ar3);
            uint32_t al0 = to_tf32(ar0 - __uint_as_float(ah0));
            uint32_t al1 = to_tf32(ar1 - __uint_as_float(ah1));
            uint32_t al2 = to_tf32(ar2 - __uint_as_float(ah2));
            uint32_t al3 = to_tf32(ar3 - __uint_as_float(ah3));
            float2 q = sp2[mt];                  // (0.5p_t0, 0.5p_t1), t0=2mt
#pragma unroll
            for (int j = 0; j < 8; j++) {
                float2 bias = *reinterpret_cast<const float2*>(
                    &sCzh[colbase + j * 8 + 2 * c]);
                float c0 = bias.x, c1 = bias.y, c2 = bias.x, c3 = bias.y;
                mma_tf32(c0, c1, c2, c3, ah0, ah1, ah2, ah3, bhi0[j], bhi1[j]);
                mma_tf32(c0, c1, c2, c3, al0, al1, al2, al3, bhi0[j], bhi1[j]);
                mma_tf32(c0, c1, c2, c3, ah0, ah1, ah2, ah3, blo0[j], blo1[j]);
                // c0 = az(t0)/2, c1 = ah(t0), c2 = az(t1)/2, c3 = ah(t1)  for (n=g, u)
                float tz0 = tanh_a(c0), th0 = tanh_a(c1);
                float tz1 = tanh_a(c2), th1 = tanh_a(c3);
                float rr0 = fmaf(-tz0, q.x, q.x);   // p*(1-sigmoid(az))
                float rr1 = fmaf(-tz1, q.y, q.y);
                acc[j] = fmaf(rr0, th0, acc[j]);
                acc[j] = fmaf(rr1, th1, acc[j]);
            }
        }
#pragma unroll
        for (int j = 0; j < 8; j++)
            sH[g][wid * 32 + j * 4 + c] = fmaxf(acc[j], 0.0f);
    }
    __syncthreads();

    // ---- epilogue: warp w -> node n0+w ----
    {
        float part[TT];
#pragma unroll
        for (int t = 0; t < TT; t++) part[t] = 0.0f;
#pragma unroll
        for (int q = 0; q < 8; q++) {
            int k = lane + 32 * q;
            float h = sH[wid][k];
            const float4* wr = reinterpret_cast<const float4*>(lin_w + k * TT);
            float4 w0 = __ldg(wr + 0);
            float4 w1 = __ldg(wr + 1);
            float4 w2 = __ldg(wr + 2);
            part[0] = fmaf(h, w0.x, part[0]);  part[1]  = fmaf(h, w0.y, part[1]);
            part[2] = fmaf(h, w0.z, part[2]);  part[3]  = fmaf(h, w0.w, part[3]);
            part[4] = fmaf(h, w1.x, part[4]);  part[5]  = fmaf(h, w1.y, part[5]);
            part[6] = fmaf(h, w1.z, part[6]);  part[7]  = fmaf(h, w1.w, part[7]);
            part[8] = fmaf(h, w2.x, part[8]);  part[9]  = fmaf(h, w2.y, part[9]);
            part[10] = fmaf(h, w2.z, part[10]); part[11] = fmaf(h, w2.w, part[11]);
        }
#pragma unroll
        for (int d = 16; d > 0; d >>= 1)
#pragma unroll
            for (int t = 0; t < TT; t++)
                part[t] += __shfl_xor_sync(0xffffffffu, part[t], d);
        if (lane < TT)
            out[(size_t)(n0 + wid) * TT + lane] = part[lane] + __ldg(lin_b + lane);
    }
}

// ---------------- launcher: memset + 2 kernels ----------------
extern "C" void kernel_launch(void* const* d_in, const int* in_sizes, int n_in,
                              void* d_out, int out_size) {
    const float* x      = (const float*)d_in[0];
    const int*   ei     = (const int*)d_in[1];
    const float* ew     = (const float*)d_in[2];
    const float* att    = (const float*)d_in[3];
    const float* Wz     = (const float*)d_in[4];
    const float* bz     = (const float*)d_in[5];
    // d_in[6..7] (Wr, br) dead: r-gate multiplies H0 == 0
    const float* Wh     = (const float*)d_in[8];
    const float* bh     = (const float*)d_in[9];
    const float* Lzw    = (const float*)d_in[10];
    const float* Lzb    = (const float*)d_in[11];
    // d_in[12..13] (Lrw, Lrb) dead
    const float* Lhw    = (const float*)d_in[14];
    const float* Lhb    = (const float*)d_in[15];
    const float* lin_w  = (const float*)d_in[16];
    const float* lin_b  = (const float*)d_in[17];
    float* out = (float*)d_out;

    void* dc_ptr = nullptr;
    cudaGetSymbolAddress(&dc_ptr, g_dc);

    cudaMemsetAsync(dc_ptr, 0, 2 * NN * sizeof(unsigned));
    k_placeprep<<<PLACE_BLKS + 19, 1024>>>(ei, ew, Wz, Lzw, bz, Lzb,
                                           Wh, Lhw, bh, Lhb, att);
    k_dense<<<NN / NPB, UU>>>((const float4*)x, lin_w, lin_b, out);
}